// round 13
// baseline (speedup 1.0000x reference)
#include <cuda_runtime.h>
#include <math.h>

#define B_ 256
#define N_ 4096
#define D_ 128
#define C_ 32
#define BSPLIT 2     // each n handled by 2 warps, each covering B/2 batches
#define NCHUNK 16    // n-dimension split for the yhat partial kernel
#define BG 4         // b rows per partial block (grid = 64 x 16 = 1024)

// Scratch (allocation-free rule: __device__ globals)
__device__ float g_partial[NCHUNK][B_][C_];  // partial y_hat accumulations
__device__ float g_psum[NCHUNK][B_];         // partial row sums of activations

// ---------------------------------------------------------------------------
// Main kernel (R3 — proven 106.6us path, DO NOT MODIFY/SPLIT): one warp owns
// (n, b-half); 128-iter b-loop; register-resident case row; streaming 512B
// delta writes; 1024 CTAs = one full wave.
// ---------------------------------------------------------------------------
__global__ void __launch_bounds__(256) main_kernel(const float* __restrict__ q,
                                                   const float* __restrict__ cases,
                                                   const float* __restrict__ fw,
                                                   const float* __restrict__ dwt,
                                                   const float* __restrict__ bias,
                                                   float* __restrict__ delta,
                                                   float* __restrict__ act)
{
    int gw   = (blockIdx.x * blockDim.x + threadIdx.x) >> 5;  // global warp id
    int lane = threadIdx.x & 31;
    int n    = gw & (N_ - 1);        // consecutive warps -> consecutive n
    int bh   = gw >> 12;             // 0 or 1
    if (bh >= BSPLIT) return;

    const float4* c4p = reinterpret_cast<const float4*>(cases + (size_t)n * D_);
    const float4* f4p = reinterpret_cast<const float4*>(fw    + (size_t)n * D_);
    const float4* w4p = reinterpret_cast<const float4*>(dwt   + (size_t)n * D_);
    float4 c4 = __ldg(c4p + lane);
    float4 fr = __ldg(f4p + lane);
    float4 dr = __ldg(w4p + lane);
    float  bn = __ldg(bias + n);

    float4 f4;
    f4.x = (fr.x > 20.0f) ? fr.x : log1pf(expf(fr.x));
    f4.y = (fr.y > 20.0f) ? fr.y : log1pf(expf(fr.y));
    f4.z = (fr.z > 20.0f) ? fr.z : log1pf(expf(fr.z));
    f4.w = (fr.w > 20.0f) ? fr.w : log1pf(expf(fr.w));

    float4 w4;
    w4.x = f4.x * (-fabsf(dr.x));
    w4.y = f4.y * (-fabsf(dr.y));
    w4.z = f4.z * (-fabsf(dr.z));
    w4.w = f4.w * (-fabsf(dr.w));

    const int b0 = bh * (B_ / BSPLIT);
    const int b1 = b0 + (B_ / BSPLIT);   // 128 iterations — do not shrink

    const float4* q4base = reinterpret_cast<const float4*>(q);
    float4*       d4base = reinterpret_cast<float4*>(delta);

    for (int b = b0; b < b1; b++) {
        float4 q4 = __ldg(q4base + (size_t)b * (D_ / 4) + lane);

        float dx = q4.x - c4.x;
        float dy = q4.y - c4.y;
        float dz = q4.z - c4.z;
        float dwv = q4.w - c4.w;
        dx *= dx; dy *= dy; dz *= dz; dwv *= dwv;

        float4 o;
        o.x = dx * f4.x; o.y = dy * f4.y; o.z = dz * f4.z; o.w = dwv * f4.w;

        float a = dx * w4.x;
        a = fmaf(dy,  w4.y, a);
        a = fmaf(dz,  w4.z, a);
        a = fmaf(dwv, w4.w, a);

        __stcs(&d4base[((size_t)b * N_ + n) * (D_ / 4) + lane], o);

        a += __shfl_xor_sync(0xffffffffu, a, 16);
        a += __shfl_xor_sync(0xffffffffu, a, 8);
        a += __shfl_xor_sync(0xffffffffu, a, 4);
        a += __shfl_xor_sync(0xffffffffu, a, 2);
        a += __shfl_xor_sync(0xffffffffu, a, 1);

        if (lane == 0) {
            float s  = a + bn;
            float av = 1.0f / (1.0f + expf(-s));
            act[(size_t)b * N_ + n] = av;   // stays L2-resident for epilogue
        }
    }
}

// ---------------------------------------------------------------------------
// yhat partials: 64 b-groups (4 b each) x 16 chunks = 1024 blocks.
// Launched with PDL: targets rows are prefetched BEFORE the grid-dependency
// sync (they don't depend on act), overlapping main's store-drain tail.
// ---------------------------------------------------------------------------
__global__ void __launch_bounds__(256) yhat_partial_kernel(const float* __restrict__ act,
                                                           const float* __restrict__ targets)
{
    int chunk = blockIdx.x & (NCHUNK - 1);
    int bg    = blockIdx.x >> 4;            // 0..63
    int b0    = bg * BG;
    int w     = threadIdx.x >> 5;
    int lane  = threadIdx.x & 31;
    int c0    = w * 4;

    const int nper = N_ / NCHUNK;           // 256
    const int nst  = chunk * nper;

    // --- pre-sync phase: prefetch this warp's 8 target rows (independent of act)
    float4 t[nper / 32];
    #pragma unroll
    for (int it = 0; it < nper / 32; it++) {
        int n = nst + it * 32 + lane;
        t[it] = __ldg(reinterpret_cast<const float4*>(targets + (size_t)n * C_ + c0));
    }

    // --- wait for main kernel's memory to be visible
    cudaGridDependencySynchronize();

    float acc[BG][4];
    float srow[BG];
    #pragma unroll
    for (int i = 0; i < BG; i++) {
        srow[i] = 0.0f;
        #pragma unroll
        for (int j = 0; j < 4; j++) acc[i][j] = 0.0f;
    }

    #pragma unroll
    for (int it = 0; it < nper / 32; it++) {
        int n = nst + it * 32 + lane;
        #pragma unroll
        for (int i = 0; i < BG; i++) {
            float a = __ldg(act + (size_t)(b0 + i) * N_ + n);
            srow[i] += a;
            acc[i][0] = fmaf(a, t[it].x, acc[i][0]);
            acc[i][1] = fmaf(a, t[it].y, acc[i][1]);
            acc[i][2] = fmaf(a, t[it].z, acc[i][2]);
            acc[i][3] = fmaf(a, t[it].w, acc[i][3]);
        }
    }

    #pragma unroll
    for (int i = 0; i < BG; i++) {
        #pragma unroll
        for (int j = 0; j < 4; j++) {
            float v = acc[i][j];
            v += __shfl_xor_sync(0xffffffffu, v, 16);
            v += __shfl_xor_sync(0xffffffffu, v, 8);
            v += __shfl_xor_sync(0xffffffffu, v, 4);
            v += __shfl_xor_sync(0xffffffffu, v, 2);
            v += __shfl_xor_sync(0xffffffffu, v, 1);
            acc[i][j] = v;
        }
        float s = srow[i];
        s += __shfl_xor_sync(0xffffffffu, s, 16);
        s += __shfl_xor_sync(0xffffffffu, s, 8);
        s += __shfl_xor_sync(0xffffffffu, s, 4);
        s += __shfl_xor_sync(0xffffffffu, s, 2);
        s += __shfl_xor_sync(0xffffffffu, s, 1);
        srow[i] = s;
    }

    if (lane == 0) {
        #pragma unroll
        for (int i = 0; i < BG; i++) {
            #pragma unroll
            for (int j = 0; j < 4; j++)
                g_partial[chunk][b0 + i][c0 + j] = acc[i][j];
            if (w == 0) g_psum[chunk][b0 + i] = srow[i];
        }
    }
}

// ---------------------------------------------------------------------------
// Final reduce: one thread per (b, c); 16-way partial sums (L2-hot).
// ---------------------------------------------------------------------------
__global__ void __launch_bounds__(256) yhat_reduce_kernel(float* __restrict__ yhat)
{
    int idx = blockIdx.x * blockDim.x + threadIdx.x;   // 0 .. B_*C_-1
    int b = idx >> 5;
    int c = idx & (C_ - 1);

    float v = 0.0f, s = 0.0f;
    #pragma unroll
    for (int k = 0; k < NCHUNK; k++) {
        v += g_partial[k][b][c];
        s += g_psum[k][b];
    }
    yhat[idx] = v / (s + 0.01f);
}

// ---------------------------------------------------------------------------
// Launch: single stream. Partial kernel uses PDL so its targets-prefetch
// overlaps the main kernel's tail; act loads happen after the dependency sync.
// ---------------------------------------------------------------------------
extern "C" void kernel_launch(void* const* d_in, const int* in_sizes, int n_in,
                              void* d_out, int out_size)
{
    const float* queries = (const float*)d_in[0];
    const float* cases   = (const float*)d_in[1];
    const float* targets = (const float*)d_in[2];
    const float* fw      = (const float*)d_in[3];
    const float* dw      = (const float*)d_in[4];
    const float* bias    = (const float*)d_in[5];

    float* out   = (float*)d_out;
    float* yhat  = out;                                   // B*C
    float* act   = out + (size_t)B_ * C_;                 // B*N
    float* delta = out + (size_t)B_ * C_ + (size_t)B_ * N_;

    int total_warps = N_ * BSPLIT;
    main_kernel<<<total_warps / 8, 256>>>(queries, cases, fw, dw, bias, delta, act);

    // PDL launch of the partial kernel
    {
        cudaLaunchConfig_t cfg = {};
        cfg.gridDim  = dim3((B_ / BG) * NCHUNK, 1, 1);    // 1024 blocks
        cfg.blockDim = dim3(256, 1, 1);
        cudaLaunchAttribute attr[1];
        attr[0].id = cudaLaunchAttributeProgrammaticStreamSerialization;
        attr[0].val.programmaticStreamSerializationAllowed = 1;
        cfg.attrs    = attr;
        cfg.numAttrs = 1;
        cudaLaunchKernelEx(&cfg, yhat_partial_kernel, act, targets);
    }

    yhat_reduce_kernel<<<(B_ * C_) / 256, 256>>>(yhat);
}

// round 14
// speedup vs baseline: 1.0394x; 1.0394x over previous
#include <cuda_runtime.h>
#include <math.h>

#define B_ 256
#define N_ 4096
#define D_ 128
#define C_ 32
#define BSPLIT 2     // each n handled by 2 warps, each covering B/2 batches
#define NCHUNK 16    // n-dimension split for the yhat partial kernel

// Scratch (allocation-free rule: __device__ globals)
__device__ float g_partial[NCHUNK][B_][C_];  // partial y_hat accumulations
__device__ float g_psum[NCHUNK][B_];         // partial row sums of activations

// ---------------------------------------------------------------------------
// Main kernel (R3 — proven, FROZEN): one warp owns (n, b-half); 128-iter
// b-loop; register-resident case row; streaming 512B delta writes; 1024 CTAs.
// ---------------------------------------------------------------------------
__global__ void __launch_bounds__(256) main_kernel(const float* __restrict__ q,
                                                   const float* __restrict__ cases,
                                                   const float* __restrict__ fw,
                                                   const float* __restrict__ dwt,
                                                   const float* __restrict__ bias,
                                                   float* __restrict__ delta,
                                                   float* __restrict__ act)
{
    int gw   = (blockIdx.x * blockDim.x + threadIdx.x) >> 5;  // global warp id
    int lane = threadIdx.x & 31;
    int n    = gw & (N_ - 1);        // consecutive warps -> consecutive n
    int bh   = gw >> 12;             // 0 or 1
    if (bh >= BSPLIT) return;

    const float4* c4p = reinterpret_cast<const float4*>(cases + (size_t)n * D_);
    const float4* f4p = reinterpret_cast<const float4*>(fw    + (size_t)n * D_);
    const float4* w4p = reinterpret_cast<const float4*>(dwt   + (size_t)n * D_);
    float4 c4 = __ldg(c4p + lane);
    float4 fr = __ldg(f4p + lane);
    float4 dr = __ldg(w4p + lane);
    float  bn = __ldg(bias + n);

    float4 f4;
    f4.x = (fr.x > 20.0f) ? fr.x : log1pf(expf(fr.x));
    f4.y = (fr.y > 20.0f) ? fr.y : log1pf(expf(fr.y));
    f4.z = (fr.z > 20.0f) ? fr.z : log1pf(expf(fr.z));
    f4.w = (fr.w > 20.0f) ? fr.w : log1pf(expf(fr.w));

    float4 w4;
    w4.x = f4.x * (-fabsf(dr.x));
    w4.y = f4.y * (-fabsf(dr.y));
    w4.z = f4.z * (-fabsf(dr.z));
    w4.w = f4.w * (-fabsf(dr.w));

    const int b0 = bh * (B_ / BSPLIT);
    const int b1 = b0 + (B_ / BSPLIT);   // 128 iterations — do not shrink

    const float4* q4base = reinterpret_cast<const float4*>(q);
    float4*       d4base = reinterpret_cast<float4*>(delta);

    for (int b = b0; b < b1; b++) {
        float4 q4 = __ldg(q4base + (size_t)b * (D_ / 4) + lane);

        float dx = q4.x - c4.x;
        float dy = q4.y - c4.y;
        float dz = q4.z - c4.z;
        float dwv = q4.w - c4.w;
        dx *= dx; dy *= dy; dz *= dz; dwv *= dwv;

        float4 o;
        o.x = dx * f4.x; o.y = dy * f4.y; o.z = dz * f4.z; o.w = dwv * f4.w;

        float a = dx * w4.x;
        a = fmaf(dy,  w4.y, a);
        a = fmaf(dz,  w4.z, a);
        a = fmaf(dwv, w4.w, a);

        __stcs(&d4base[((size_t)b * N_ + n) * (D_ / 4) + lane], o);

        a += __shfl_xor_sync(0xffffffffu, a, 16);
        a += __shfl_xor_sync(0xffffffffu, a, 8);
        a += __shfl_xor_sync(0xffffffffu, a, 4);
        a += __shfl_xor_sync(0xffffffffu, a, 2);
        a += __shfl_xor_sync(0xffffffffu, a, 1);

        if (lane == 0) {
            float s  = a + bn;
            float av = 1.0f / (1.0f + expf(-s));
            act[(size_t)b * N_ + n] = av;   // stays L2-resident for epilogue
        }
    }
}

// ---------------------------------------------------------------------------
// yhat partials: 32 b-groups x 16 chunks = 512 blocks (R3 grid), but each
// lane now owns a QUAD of n -> act loads are float4, loop is 2 iterations.
// Warp w owns 4 c-columns.
// ---------------------------------------------------------------------------
__global__ void __launch_bounds__(256) yhat_partial_kernel(const float* __restrict__ act,
                                                           const float* __restrict__ targets)
{
    int chunk = blockIdx.x & (NCHUNK - 1);
    int bg    = blockIdx.x >> 4;            // 0..31
    int b0    = bg * 8;
    int w     = threadIdx.x >> 5;
    int lane  = threadIdx.x & 31;
    int c0    = w * 4;

    const int nper = N_ / NCHUNK;           // 256
    const int nst  = chunk * nper;

    float acc[8][4];
    float srow[8];
    #pragma unroll
    for (int i = 0; i < 8; i++) {
        srow[i] = 0.0f;
        #pragma unroll
        for (int j = 0; j < 4; j++) acc[i][j] = 0.0f;
    }

    #pragma unroll
    for (int it = 0; it < nper / 128; it++) {          // 2 iterations
        int n = nst + it * 128 + lane * 4;             // lane owns n..n+3
        const float* tb = targets + (size_t)n * C_ + c0;
        float4 t0 = __ldg(reinterpret_cast<const float4*>(tb));
        float4 t1 = __ldg(reinterpret_cast<const float4*>(tb + C_));
        float4 t2 = __ldg(reinterpret_cast<const float4*>(tb + 2 * C_));
        float4 t3 = __ldg(reinterpret_cast<const float4*>(tb + 3 * C_));

        #pragma unroll
        for (int i = 0; i < 8; i++) {
            float4 a = __ldg(reinterpret_cast<const float4*>(act + (size_t)(b0 + i) * N_ + n));
            srow[i] += (a.x + a.y) + (a.z + a.w);
            acc[i][0] = fmaf(a.x, t0.x, fmaf(a.y, t1.x, fmaf(a.z, t2.x, fmaf(a.w, t3.x, acc[i][0]))));
            acc[i][1] = fmaf(a.x, t0.y, fmaf(a.y, t1.y, fmaf(a.z, t2.y, fmaf(a.w, t3.y, acc[i][1]))));
            acc[i][2] = fmaf(a.x, t0.z, fmaf(a.y, t1.z, fmaf(a.z, t2.z, fmaf(a.w, t3.z, acc[i][2]))));
            acc[i][3] = fmaf(a.x, t0.w, fmaf(a.y, t1.w, fmaf(a.z, t2.w, fmaf(a.w, t3.w, acc[i][3]))));
        }
    }

    #pragma unroll
    for (int i = 0; i < 8; i++) {
        #pragma unroll
        for (int j = 0; j < 4; j++) {
            float v = acc[i][j];
            v += __shfl_xor_sync(0xffffffffu, v, 16);
            v += __shfl_xor_sync(0xffffffffu, v, 8);
            v += __shfl_xor_sync(0xffffffffu, v, 4);
            v += __shfl_xor_sync(0xffffffffu, v, 2);
            v += __shfl_xor_sync(0xffffffffu, v, 1);
            acc[i][j] = v;
        }
        float s = srow[i];
        s += __shfl_xor_sync(0xffffffffu, s, 16);
        s += __shfl_xor_sync(0xffffffffu, s, 8);
        s += __shfl_xor_sync(0xffffffffu, s, 4);
        s += __shfl_xor_sync(0xffffffffu, s, 2);
        s += __shfl_xor_sync(0xffffffffu, s, 1);
        srow[i] = s;
    }

    if (lane == 0) {
        #pragma unroll
        for (int i = 0; i < 8; i++) {
            #pragma unroll
            for (int j = 0; j < 4; j++)
                g_partial[chunk][b0 + i][c0 + j] = acc[i][j];
            if (w == 0) g_psum[chunk][b0 + i] = srow[i];
        }
    }
}

// ---------------------------------------------------------------------------
// Final reduce: one thread per (b, c); 16-way partial sums (L2-hot).
// ---------------------------------------------------------------------------
__global__ void __launch_bounds__(256) yhat_reduce_kernel(float* __restrict__ yhat)
{
    int idx = blockIdx.x * blockDim.x + threadIdx.x;   // 0 .. B_*C_-1
    int b = idx >> 5;
    int c = idx & (C_ - 1);

    float v = 0.0f, s = 0.0f;
    #pragma unroll
    for (int k = 0; k < NCHUNK; k++) {
        v += g_partial[k][b][c];
        s += g_psum[k][b];
    }
    yhat[idx] = v / (s + 0.01f);
}

// ---------------------------------------------------------------------------
// Launch: single stream, three kernels (R3 structure — proven).
// ---------------------------------------------------------------------------
extern "C" void kernel_launch(void* const* d_in, const int* in_sizes, int n_in,
                              void* d_out, int out_size)
{
    const float* queries = (const float*)d_in[0];
    const float* cases   = (const float*)d_in[1];
    const float* targets = (const float*)d_in[2];
    const float* fw      = (const float*)d_in[3];
    const float* dw      = (const float*)d_in[4];
    const float* bias    = (const float*)d_in[5];

    float* out   = (float*)d_out;
    float* yhat  = out;                                   // B*C
    float* act   = out + (size_t)B_ * C_;                 // B*N
    float* delta = out + (size_t)B_ * C_ + (size_t)B_ * N_;

    int total_warps = N_ * BSPLIT;
    main_kernel<<<total_warps / 8, 256>>>(queries, cases, fw, dw, bias, delta, act);
    yhat_partial_kernel<<<(B_ / 8) * NCHUNK, 256>>>(act, targets);
    yhat_reduce_kernel<<<(B_ * C_) / 256, 256>>>(yhat);
}